// round 15
// baseline (speedup 1.0000x reference)
#include <cuda_runtime.h>
#include <cuda_fp16.h>
#include <cstdint>

#define N_NODES 100000
#define N_EDGES 1600000
#define F 128
#define NB 98          // ceil(100000/1024) scan blocks
#define GB_TILES 782   // ceil(100000/128), full 128-col tile
#define ACT_ROWS (N_NODES + 128)          // pad: OOB tile rows stay in-bounds
#define ACT_STRIDE ((size_t)ACT_ROWS * 128)
#define PREPX_ITEMS (N_NODES * 16)
#define PREPW_ITEMS (7 * 128 * 16)
#define PREP_ITEMS (PREPX_ITEMS + PREPW_ITEMS)
#define PREP_B ((PREP_ITEMS + 255) / 256)
#define HIST_B ((N_EDGES + 255) / 256)
#define SCAT_B ((N_EDGES + 255) / 256)
#define ZERO_B ((N_NODES + 255) / 256)

// ---------------- scratch (static __device__, allocation-free) ----------------
// fp16 activation planes, row = 128 fp16 (256B). ids: 0 = x, 1 = xp, 2 = h1, 3 = h2
__device__ __half d_act[4 * ACT_STRIDE];
// weights: 7 slices x [n=128][k=128] fp16
__device__ __half d_wtp[7 * 128 * 128];
__device__ __half d_g[(size_t)N_NODES * F];   // fp16 messages
__device__ float d_dinv[N_NODES];
__device__ int   d_cnt[N_NODES];       // zero-init at load; re-zeroed at end of each run
__device__ int   d_rowptr[N_NODES + 1];
__device__ int   d_cursor[N_NODES];
__device__ int   d_ssrc[N_EDGES];
__device__ int   d_partial[NB];

__device__ __forceinline__ uint32_t smem_u32(const void* p) {
    uint32_t a;
    asm("{ .reg .u64 t; cvta.to.shared.u64 t, %1; cvt.u32.u64 %0, t; }" : "=r"(a) : "l"(p));
    return a;
}
__device__ __forceinline__ void ldsm_x4(uint32_t* r, uint32_t addr) {
    asm volatile("ldmatrix.sync.aligned.m8n8.x4.shared.b16 {%0,%1,%2,%3}, [%4];"
        : "=r"(r[0]), "=r"(r[1]), "=r"(r[2]), "=r"(r[3]) : "r"(addr));
}
__device__ __forceinline__ void mma16816(float* d, const uint32_t* a, const uint32_t* b) {
    asm volatile(
        "mma.sync.aligned.m16n8k16.row.col.f32.f16.f16.f32 "
        "{%0,%1,%2,%3}, {%4,%5,%6,%7}, {%8,%9}, {%0,%1,%2,%3};"
        : "+f"(d[0]), "+f"(d[1]), "+f"(d[2]), "+f"(d[3])
        : "r"(a[0]), "r"(a[1]), "r"(a[2]), "r"(a[3]), "r"(b[0]), "r"(b[1]));
}
__device__ __forceinline__ void cpa16(uint32_t dst, const void* src) {
    asm volatile("cp.async.cg.shared.global [%0], [%1], 16;" :: "r"(dst), "l"(src));
}
#define CP_COMMIT() asm volatile("cp.async.commit_group;" ::: "memory")
#define CP_WAIT1()  asm volatile("cp.async.wait_group 1;" ::: "memory")
#define CP_WAIT0()  asm volatile("cp.async.wait_group 0;" ::: "memory")

__device__ __forceinline__ uint32_t pack_h2(float x, float y) {
    __half2 t = __floats2half2_rn(x, y);
    return *(uint32_t*)&t;
}
__device__ __forceinline__ float2 unpack_h2(uint32_t v) {
    return __half22float2(*(__half2*)&v);
}

// ---------------- launch 1: prep planes + weights, and hist (extra blocks) ------
__global__ void k_prep_hist(const float* __restrict__ x,
                            const float* __restrict__ pW, const float* __restrict__ w1,
                            const float* __restrict__ w2, const float* __restrict__ w3,
                            const int* __restrict__ dst) {
    if (blockIdx.x < PREP_B) {
        int idx = blockIdx.x * 256 + threadIdx.x;
        if (idx < PREPX_ITEMS) {
            int row = idx >> 4;
            int k0 = (idx & 15) * 8;
            const float* src = x + (size_t)row * F + k0;
            uint32_t h[4];
#pragma unroll
            for (int j = 0; j < 4; j++) h[j] = pack_h2(src[j * 2], src[j * 2 + 1]);
            *(uint4*)(d_act + (size_t)row * 128 + k0) = make_uint4(h[0], h[1], h[2], h[3]);
        } else if (idx < PREP_ITEMS) {
            int j = idx - PREPX_ITEMS;
            int slice = j >> 11;
            int rem = j & 2047;
            int n = rem >> 4;
            int k0 = (rem & 15) * 8;
            const float* src; int kg0;
            if (slice == 0)      { src = pW; kg0 = 0; }
            else if (slice == 1) { src = w1; kg0 = 0; }
            else if (slice < 4)  { src = w2; kg0 = (slice - 2) * 128; }
            else                 { src = w3; kg0 = (slice - 4) * 128; }
            uint32_t hi[4];
#pragma unroll
            for (int jj = 0; jj < 4; jj++) {
                float a = src[(size_t)(kg0 + k0 + jj * 2) * 128 + n];
                float b = src[(size_t)(kg0 + k0 + jj * 2 + 1) * 128 + n];
                hi[jj] = pack_h2(a, b);
            }
            *(uint4*)(d_wtp + (size_t)slice * 128 * 128 + (size_t)n * 128 + k0) =
                make_uint4(hi[0], hi[1], hi[2], hi[3]);
        }
    } else {
        int e = (blockIdx.x - PREP_B) * 256 + threadIdx.x;
        if (e < N_EDGES) {
            int d = dst[e];
            if (d >= 0 && d < N_NODES) atomicAdd(&d_cnt[d], 1);
        }
    }
}

// ---------------- launch 2: per-block partial sums + dinv (extra blocks) --------
__global__ void k_partial_dinv() {
    if (blockIdx.x < NB) {
        __shared__ int s[1024];
        int i = blockIdx.x * 1024 + threadIdx.x;
        s[threadIdx.x] = (i < N_NODES) ? d_cnt[i] : 0;
        __syncthreads();
        for (int off = 512; off > 0; off >>= 1) {
            if (threadIdx.x < off) s[threadIdx.x] += s[threadIdx.x + off];
            __syncthreads();
        }
        if (threadIdx.x == 0) d_partial[blockIdx.x] = s[0];
    } else {
        int v = (blockIdx.x - NB) * 1024 + threadIdx.x;
        if (v < N_NODES) d_dinv[v] = rsqrtf((float)(d_cnt[v] + 1));
    }
}

// ---------------- launch 4: scatter + re-zero cnt (extra blocks) ----------------
__global__ void k_scatter_zero(const int* __restrict__ src, const int* __restrict__ dst) {
    if (blockIdx.x < SCAT_B) {
        int e = blockIdx.x * 256 + threadIdx.x;
        if (e < N_EDGES) {
            int d = dst[e];
            int s = src[e];
            if (d >= 0 && d < N_NODES && s >= 0 && s < N_NODES) {
                int pos = atomicAdd(&d_cursor[d], 1);
                d_ssrc[pos] = s;
            }
        }
    } else {
        int i = (blockIdx.x - SCAT_B) * 256 + threadIdx.x;
        if (i < N_NODES) d_cnt[i] = 0;     // leave zero for next graph replay
    }
}

// ---------------- HMMA GEMM, fp16 single-product, 2-stage cp.async, 128x128 -----
// launch 3 (fused=1): grid 2*GB_TILES + NB; last NB blocks run CSR row-scan.
// stage s at s*32768: A[128 rows][128B] (16KB), W[128 rows][128B] at +16384 (16KB)
#define STAGE_BYTES 32768
#define SMEM_TOTAL (2 * STAGE_BYTES)

__device__ void scan_rowptr_block(int j) {
    __shared__ int ssum[256];
    __shared__ int sP;
    int t = threadIdx.x;
    // prefix of prior blocks' partials
    if (t < 32) {
        int p = 0;
        for (int i = t; i < j; i += 32) p += d_partial[i];
#pragma unroll
        for (int off = 16; off > 0; off >>= 1) p += __shfl_down_sync(0xFFFFFFFFu, p, off);
        if (t == 0) sP = p;
    }
    int base = j * 1024 + t * 4;
    int v0 = (base + 0 < N_NODES) ? d_cnt[base + 0] : 0;
    int v1 = (base + 1 < N_NODES) ? d_cnt[base + 1] : 0;
    int v2 = (base + 2 < N_NODES) ? d_cnt[base + 2] : 0;
    int v3 = (base + 3 < N_NODES) ? d_cnt[base + 3] : 0;
    int tot = v0 + v1 + v2 + v3;
    ssum[t] = tot;
    __syncthreads();
    for (int off = 1; off < 256; off <<= 1) {
        int u = (t >= off) ? ssum[t - off] : 0;
        __syncthreads();
        ssum[t] += u;
        __syncthreads();
    }
    int excl = ssum[t] - tot + sP;
    int p0 = excl, p1 = excl + v0, p2 = p1 + v1, p3 = p2 + v2;
    if (base + 0 < N_NODES) { d_rowptr[base + 0] = p0; d_cursor[base + 0] = p0; }
    if (base + 1 < N_NODES) { d_rowptr[base + 1] = p1; d_cursor[base + 1] = p1; }
    if (base + 2 < N_NODES) { d_rowptr[base + 2] = p2; d_cursor[base + 2] = p2; }
    if (base + 3 < N_NODES) { d_rowptr[base + 3] = p3; d_cursor[base + 3] = p3; }
    if (j == NB - 1 && t == 255) d_rowptr[N_NODES] = sP + ssum[255];
}

// fused=1: half 0 -> wslice0+0, epi 2 (xp); half 1 -> wslice0+1, epi 1 (g); +NB scan blocks
// epi: 1 = d_g fp16, scale row by dinv; 2 = xp fp16 plane, bias + relu
__global__ __launch_bounds__(256, 2)
void k_mma(int aid0, int aid1, int aid2, int nslices,
           int wslice0, int epi, int fused, const float* __restrict__ bias)
{
    if (fused && blockIdx.x >= 2 * GB_TILES) {
        scan_rowptr_block(blockIdx.x - 2 * GB_TILES);
        return;
    }
    extern __shared__ char smem[];
    const uint32_t sb = smem_u32(smem);
    const int tid = threadIdx.x;
    const int lane = tid & 31;
    const int warp = tid >> 5;
    const int half_id = fused ? (blockIdx.x >= GB_TILES ? 1 : 0) : 0;
    const int bx = fused ? (blockIdx.x - half_id * GB_TILES) : blockIdx.x;
    const int brow = bx * 128;
    const int wbase = wslice0 + half_id;
    const int epi_eff = fused ? (half_id ? 1 : 2) : epi;
    const int warp_m = (warp >> 1) * 32;
    const int warp_n = (warp & 1) * 64;

    float acc[2][8][4];
#pragma unroll
    for (int mb = 0; mb < 2; mb++)
#pragma unroll
        for (int nb = 0; nb < 8; nb++)
#pragma unroll
            for (int q = 0; q < 4; q++) acc[mb][nb][q] = 0.0f;

    const int aids[3] = {aid0, aid1, aid2};
    const int T = nslices * 2;          // k64 chunks

    const int st_row = tid >> 3;
    const int st_ch  = tid & 7;

    const int rowA = warp_m + (lane & 15);
    const int swA = rowA & 7;
    const int chA = lane >> 4;
    const int rowB = warp_n + (lane & 7) + ((lane >> 4) << 3);
    const int swB = lane & 7;
    const int chB = (lane >> 3) & 1;

    auto stage = [&](int t, int buf) {
        int s = t >> 1, c = t & 1;
        const __half* Ag = d_act + (size_t)aids[s] * ACT_STRIDE;
        const __half* Wg = d_wtp + (size_t)(wbase + s) * 128 * 128;
        uint32_t abuf = sb + buf * STAGE_BYTES;
        uint32_t wbuf = abuf + 16384;
#pragma unroll
        for (int it = 0; it < 4; it++) {
            int row = st_row + it * 32;
            const char* src = (const char*)(Ag + (size_t)(brow + row) * 128 + c * 64) + st_ch * 16;
            cpa16(abuf + row * 128 + ((st_ch ^ (row & 7)) << 4), src);
        }
#pragma unroll
        for (int it = 0; it < 4; it++) {
            int n = st_row + it * 32;
            const __half* wrow = Wg + (size_t)n * 128 + c * 64;
            cpa16(wbuf + n * 128 + ((st_ch ^ (n & 7)) << 4), (const char*)wrow + st_ch * 16);
        }
    };

    stage(0, 0); CP_COMMIT();

    for (int t = 0; t < T; t++) {
        const int buf = t & 1;
        if (t + 1 < T) { stage(t + 1, buf ^ 1); CP_COMMIT(); CP_WAIT1(); }
        else           { CP_WAIT0(); }
        __syncthreads();

        const uint32_t abase = sb + buf * STAGE_BYTES + rowA * 128;
        const uint32_t bbase = sb + buf * STAGE_BYTES + 16384 + rowB * 128;
#pragma unroll
        for (int ks = 0; ks < 4; ks++) {
            uint32_t ah[2][4];
            const int lA = ks * 2 + chA;
#pragma unroll
            for (int mb = 0; mb < 2; mb++)
                ldsm_x4(ah[mb], abase + mb * 2048 + ((lA ^ swA) << 4));
            const int lB = ks * 2 + chB;
            uint32_t bh[4][4];
#pragma unroll
            for (int nq = 0; nq < 4; nq++)
                ldsm_x4(bh[nq], bbase + nq * 2048 + ((lB ^ swB) << 4));
#pragma unroll
            for (int nq = 0; nq < 4; nq++)
#pragma unroll
                for (int mb = 0; mb < 2; mb++) {
                    mma16816(acc[mb][nq * 2],     ah[mb], bh[nq]);
                    mma16816(acc[mb][nq * 2 + 1], ah[mb], bh[nq] + 2);
                }
        }
        __syncthreads();
    }

    const int ncol0 = warp_n + (lane & 3) * 2;
#pragma unroll
    for (int mb = 0; mb < 2; mb++) {
        int rbase = brow + warp_m + mb * 16 + (lane >> 2);
#pragma unroll
        for (int half = 0; half < 2; half++) {
            int grow = rbase + half * 8;
            if (grow >= N_NODES) continue;
            int q0 = half * 2;
            if (epi_eff == 1) {
                float dv = d_dinv[grow];
#pragma unroll
                for (int nb = 0; nb < 8; nb++) {
                    uint32_t o = pack_h2(acc[mb][nb][q0] * dv, acc[mb][nb][q0 + 1] * dv);
                    *(uint32_t*)(d_g + (size_t)grow * F + ncol0 + nb * 8) = o;
                }
            } else {
                __half* prow = d_act + ACT_STRIDE + (size_t)grow * 128;  // plane 1 = xp
#pragma unroll
                for (int nb = 0; nb < 8; nb++) {
                    int n = ncol0 + nb * 8;
                    float o0 = fmaxf(acc[mb][nb][q0]     + bias[n],     0.0f);
                    float o1 = fmaxf(acc[mb][nb][q0 + 1] + bias[n + 1], 0.0f);
                    *(uint32_t*)(prow + n) = pack_h2(o0, o1);
                }
            }
        }
    }
}

// ---------------- aggregation (1 warp/node, independent) ------------------------
// out[v] = relu(dinv[v]*(sum_in g[u] + g[v]) + b); fp16 plane (planeId>=0) or fp32 out
__global__ __launch_bounds__(256) void k_agg(int planeId,
                                             float* __restrict__ out_ext,
                                             const float* __restrict__ bias)
{
    const __half* g = d_g;
    int v = (blockIdx.x * blockDim.x + threadIdx.x) >> 5;
    int lane = threadIdx.x & 31;
    if (v >= N_NODES) return;

    int beg = d_rowptr[v];
    int end = d_rowptr[v + 1];

    uint2 sv = *(const uint2*)(g + (size_t)v * F + lane * 4);   // self term
    float2 p0 = unpack_h2(sv.x), p1 = unpack_h2(sv.y);
    float a0 = p0.x, a1 = p0.y, a2 = p1.x, a3 = p1.y;

    int e = beg;
    for (; e + 3 < end; e += 4) {
        int u0 = __ldg(&d_ssrc[e]);
        int u1 = __ldg(&d_ssrc[e + 1]);
        int u2 = __ldg(&d_ssrc[e + 2]);
        int u3 = __ldg(&d_ssrc[e + 3]);
        uint2 t0 = *(const uint2*)(g + (size_t)u0 * F + lane * 4);
        uint2 t1 = *(const uint2*)(g + (size_t)u1 * F + lane * 4);
        uint2 t2 = *(const uint2*)(g + (size_t)u2 * F + lane * 4);
        uint2 t3 = *(const uint2*)(g + (size_t)u3 * F + lane * 4);
        float2 q0, q1;
        q0 = unpack_h2(t0.x); q1 = unpack_h2(t0.y);
        a0 += q0.x; a1 += q0.y; a2 += q1.x; a3 += q1.y;
        q0 = unpack_h2(t1.x); q1 = unpack_h2(t1.y);
        a0 += q0.x; a1 += q0.y; a2 += q1.x; a3 += q1.y;
        q0 = unpack_h2(t2.x); q1 = unpack_h2(t2.y);
        a0 += q0.x; a1 += q0.y; a2 += q1.x; a3 += q1.y;
        q0 = unpack_h2(t3.x); q1 = unpack_h2(t3.y);
        a0 += q0.x; a1 += q0.y; a2 += q1.x; a3 += q1.y;
    }
    for (; e < end; e++) {
        int u = __ldg(&d_ssrc[e]);
        uint2 t = *(const uint2*)(g + (size_t)u * F + lane * 4);
        float2 q0 = unpack_h2(t.x), q1 = unpack_h2(t.y);
        a0 += q0.x; a1 += q0.y; a2 += q1.x; a3 += q1.y;
    }

    float dv = d_dinv[v];
    float4 b = *(const float4*)(bias + lane * 4);
    float o0 = fmaxf(fmaf(dv, a0, b.x), 0.0f);
    float o1 = fmaxf(fmaf(dv, a1, b.y), 0.0f);
    float o2 = fmaxf(fmaf(dv, a2, b.z), 0.0f);
    float o3 = fmaxf(fmaf(dv, a3, b.w), 0.0f);

    if (planeId < 0) {
        *(float4*)(out_ext + (size_t)v * F + lane * 4) = make_float4(o0, o1, o2, o3);
    } else {
        __half* prow = d_act + (size_t)planeId * ACT_STRIDE + (size_t)v * 128;
        *(uint2*)(prow + lane * 4) = make_uint2(pack_h2(o0, o1), pack_h2(o2, o3));
    }
}

// ---------------- launch ----------------
extern "C" void kernel_launch(void* const* d_in, const int* in_sizes, int n_in,
                              void* d_out, int out_size)
{
    const float* x     = (const float*)d_in[0];
    const int*   ei    = (const int*)d_in[1];     // int32: JAX x64 disabled
    const float* projW = (const float*)d_in[2];
    const float* projb = (const float*)d_in[3];
    const float* W1    = (const float*)d_in[4];
    const float* b1    = (const float*)d_in[5];
    const float* W2    = (const float*)d_in[6];
    const float* b2    = (const float*)d_in[7];
    const float* W3    = (const float*)d_in[8];
    const float* b3    = (const float*)d_in[9];
    float* out = (float*)d_out;

    const int* src = ei;
    const int* dst = ei + N_EDGES;

    cudaFuncSetAttribute(k_mma, cudaFuncAttributeMaxDynamicSharedMemorySize, SMEM_TOTAL);

    // 1: planes + weights + hist (d_cnt zero from init / previous replay)
    k_prep_hist<<<PREP_B + HIST_B, 256>>>(x, projW, W1, W2, W3, dst);
    // 2: per-block partial sums + dinv
    k_partial_dinv<<<2 * NB, 1024>>>();
    // 3: fused GEMM1 (xp + g) + CSR row-scan blocks
    k_mma<<<2 * GB_TILES + NB, 256, SMEM_TOTAL>>>(0, 0, 0, 1, 0, 0, 1, projb);
    // 4: scatter + re-zero d_cnt
    k_scatter_zero<<<SCAT_B + ZERO_B, 256>>>(src, dst);

    int AGG_BLOCKS = (N_NODES * 32 + 255) / 256;

    // 5: h1 = relu(dinv*agg(g)+b1) -> plane 2
    k_agg<<<AGG_BLOCKS, 256>>>(2, nullptr, b1);
    // 6: layer 2 GEMM: g = dinv*(xp@W2a + h1@W2b)
    k_mma<<<GB_TILES, 256, SMEM_TOTAL>>>(1, 2, 0, 2, 2, 1, 0, nullptr);
    // 7: h2 -> plane 3
    k_agg<<<AGG_BLOCKS, 256>>>(3, nullptr, b2);
    // 8: layer 3 GEMM: g = dinv*(xp@W3a + h1@W3b + h2@W3c)
    k_mma<<<GB_TILES, 256, SMEM_TOTAL>>>(1, 2, 3, 3, 4, 1, 0, nullptr);
    // 9: final output
    k_agg<<<AGG_BLOCKS, 256>>>(-1, out, b3);
}